// round 7
// baseline (speedup 1.0000x reference)
#include <cuda_runtime.h>

#define NN 50000
#define EE 800000
#define GG 500
#define CH 128
#define EF 16
#define NL 4
#define NC 10
#define BN_EPS 1e-5f

// packed-f32x2 FMA (Blackwell): d.{lo,hi} += a.{lo,hi} * b.{lo,hi}
#define FMA2(d, a, b) asm("fma.rn.f32x2 %0, %1, %2, %0;" : "+l"(d) : "l"(a), "l"(b))

#define TR 8            // rows per warp
#define NWARP 4         // warps per block
#define TILE (NWARP * TR)   // 32 rows per block
#define XSW (2 * CH)    // xs_dup row stride in floats (each value duplicated)

// ------------------------- scratch (device globals, no allocation) ---------
__device__ __align__(16) float g_h[NN * CH];
__device__ __align__(16) float g_z[NN * CH];
__device__ __align__(16) float g_ea[NN * EF];
__device__ int   g_deg[NN];
__device__ int   g_rowptr[NN + 1];
__device__ int   g_cursor[NN];
__device__ int   g_col[EE];   // CSR: src sorted by dst
__device__ int   g_eid[EE];   // CSR: edge id sorted by dst
__device__ int   g_bsum[64];
__device__ __align__(16) float g_stats[NL * 2 * CH];
__device__ __align__(16) float g_pooled[(NL + 1) * GG * CH];

// ------------------------- degree count ------------------------------------
__global__ void k_deg(const int* __restrict__ ei) {
    int e = blockIdx.x * blockDim.x + threadIdx.x;
    if (e >= EE) return;
    atomicAdd(&g_deg[ei[EE + e]], 1);
}

// ------------------------- scan pass 1: per-block sums ---------------------
__global__ void k_scan1() {
    __shared__ int s[1024];
    int i = blockIdx.x * 1024 + threadIdx.x;
    s[threadIdx.x] = (i < NN) ? g_deg[i] : 0;
    __syncthreads();
    for (int off = 512; off > 0; off >>= 1) {
        if (threadIdx.x < off) s[threadIdx.x] += s[threadIdx.x + off];
        __syncthreads();
    }
    if (threadIdx.x == 0) g_bsum[blockIdx.x] = s[0];
}

// ------------- scan pass 2: per-block base + local scan --------------------
__global__ void k_scan3(int nb) {
    __shared__ int s[1024];
    __shared__ int base;
    if (threadIdx.x == 0) {
        int run = 0;
        for (int b = 0; b < blockIdx.x; b++) run += g_bsum[b];
        base = run;
        if (blockIdx.x == 0) g_rowptr[NN] = EE;
    }
    int i = blockIdx.x * 1024 + threadIdx.x;
    int v = (i < NN) ? g_deg[i] : 0;
    s[threadIdx.x] = v;
    __syncthreads();
    for (int off = 1; off < 1024; off <<= 1) {
        int t = (threadIdx.x >= off) ? s[threadIdx.x - off] : 0;
        __syncthreads();
        s[threadIdx.x] += t;
        __syncthreads();
    }
    if (i < NN) {
        int r = s[threadIdx.x] - v + base;
        g_rowptr[i] = r;
        g_cursor[i] = r;
    }
}

// ------------------------- CSR fill ----------------------------------------
__global__ void k_fill(const int* __restrict__ ei) {
    int e = blockIdx.x * blockDim.x + threadIdx.x;
    if (e >= EE) return;
    int d = ei[EE + e];
    int pos = atomicAdd(&g_cursor[d], 1);
    g_col[pos] = ei[e];
    g_eid[pos] = e;
}

// ------------------------- ea = segment_sum(edge_attr, dst) ----------------
__global__ void k_ea(const float* __restrict__ eattr) {
    int idx = blockIdx.x * blockDim.x + threadIdx.x;
    int n = idx >> 4;
    if (n >= NN) return;
    int k = idx & 15;
    int beg = g_rowptr[n], end = g_rowptr[n + 1];
    float a0 = 0.f, a1 = 0.f;
    int e = beg;
    for (; e + 2 <= end; e += 2) {
        int i0 = g_eid[e], i1 = g_eid[e + 1];
        a0 += eattr[(size_t)i0 * EF + k];
        a1 += eattr[(size_t)i1 * EF + k];
    }
    if (e < end) a0 += eattr[(size_t)g_eid[e] * EF + k];
    g_ea[(size_t)n * EF + k] = a0 + a1;
}

// --------- duplicate-store of a float4 into xs_dup (x,x,y,y,z,z,w,w) -------
__device__ __forceinline__ void dup_store(float* __restrict__ xsd, int row, int lane,
                                          float4 v) {
    float4 d0 = make_float4(v.x, v.x, v.y, v.y);
    float4 d1 = make_float4(v.z, v.z, v.w, v.w);
    *(float4*)&xsd[row * XSW + lane * 8] = d0;
    *(float4*)&xsd[row * XSW + lane * 8 + 4] = d1;
}

// ===================== GEMM core: dup-x, pack-free f32x2 ====================
// 4 warps; warp -> 8 rows; lane -> cols {4*lane..4*lane+3} as two f32x2 pairs.
// x is pre-duplicated in smem so both FMA2 operands are straight LDS.
template <bool STATS>
__device__ __forceinline__ void gemm_tile_dup(
    const float* __restrict__ Ws, const float* __restrict__ xsd,
    unsigned long long bias0, unsigned long long bias1,
    int tile, int r0, int c0, float* __restrict__ Z,
    float* cs, float* cq) {

    unsigned long long acc[TR][2];
#pragma unroll
    for (int r = 0; r < TR; r++) { acc[r][0] = bias0; acc[r][1] = bias1; }

#pragma unroll 2
    for (int k = 0; k < CH; k += 4) {
        ulonglong2 xa[TR], xb[TR];   // dup pairs: xa={k,k+1}, xb={k+2,k+3}
#pragma unroll
        for (int r = 0; r < TR; r++) {
            const float* p = &xsd[(r0 + r) * XSW + 2 * k];
            xa[r] = *(const ulonglong2*)p;
            xb[r] = *(const ulonglong2*)(p + 4);
        }
#pragma unroll
        for (int kk = 0; kk < 4; kk++) {
            ulonglong2 w2 = *(const ulonglong2*)&Ws[(k + kk) * CH + c0];
#pragma unroll
            for (int r = 0; r < TR; r++) {
                unsigned long long xd = (kk == 0) ? xa[r].x : (kk == 1) ? xa[r].y
                                      : (kk == 2) ? xb[r].x : xb[r].y;
                FMA2(acc[r][0], xd, w2.x);
                FMA2(acc[r][1], xd, w2.y);
            }
        }
    }

#pragma unroll
    for (int r = 0; r < TR; r++) {
        int m = tile + r0 + r;
        if (m < NN) {
            ulonglong2 o;
            o.x = acc[r][0]; o.y = acc[r][1];
            *(ulonglong2*)(Z + (size_t)m * CH + c0) = o;
            if (STATS) {
                float a0 = __uint_as_float((unsigned)acc[r][0]);
                float a1 = __uint_as_float((unsigned)(acc[r][0] >> 32));
                float a2 = __uint_as_float((unsigned)acc[r][1]);
                float a3 = __uint_as_float((unsigned)(acc[r][1] >> 32));
                cs[0] += a0; cq[0] += a0 * a0;
                cs[1] += a1; cq[1] += a1 * a1;
                cs[2] += a2; cq[2] += a2 * a2;
                cs[3] += a3; cq[3] += a3 * a3;
            }
        }
    }
}

// 128-thread stats flush (256 accumulator slots)
__device__ __forceinline__ void stats_flush(float* sr, int c0, int tid,
                                            const float* cs, const float* cq,
                                            float* __restrict__ stats) {
    sr[tid] = 0.f;
    sr[tid + 128] = 0.f;
    __syncthreads();
#pragma unroll
    for (int j = 0; j < 4; j++) {
        atomicAdd(&sr[c0 + j], cs[j]);
        atomicAdd(&sr[CH + c0 + j], cq[j]);
    }
    __syncthreads();
    atomicAdd(&stats[tid], sr[tid]);
    atomicAdd(&stats[tid + 128], sr[tid + 128]);
}

// ------------------------- plain GEMM (embedding) ---------------------------
__global__ void __launch_bounds__(128, 2)
k_gemm(const float* __restrict__ X, const float* __restrict__ W,
       const float* __restrict__ B, float* __restrict__ Z) {
    extern __shared__ float sm[];
    float* Ws  = sm;                  // 128*128
    float* bs  = Ws + CH * CH;        // 128
    float* xsd = bs + CH;             // TILE*256 (duplicated)

    for (int i = threadIdx.x; i < CH * CH; i += 128) Ws[i] = W[i];
    if (threadIdx.x < CH) bs[threadIdx.x] = B[threadIdx.x];
    __syncthreads();

    int warp = threadIdx.x >> 5, lane = threadIdx.x & 31;
    int c0 = lane * 4, r0 = warp * TR;
    unsigned long long bias0 = *(const unsigned long long*)&bs[c0];
    unsigned long long bias1 = *(const unsigned long long*)&bs[c0 + 2];
    float cs[4], cq[4];

    for (int tile = blockIdx.x * TILE; tile < NN; tile += gridDim.x * TILE) {
#pragma unroll
        for (int r = 0; r < TR; r++) {
            int m = tile + r0 + r;
            float4 v = make_float4(0.f, 0.f, 0.f, 0.f);
            if (m < NN) v = *(const float4*)(X + (size_t)m * CH + c0);
            dup_store(xsd, r0 + r, lane, v);
        }
        __syncthreads();
        gemm_tile_dup<false>(Ws, xsd, bias0, bias1, tile, r0, c0, Z, cs, cq);
        __syncthreads();
    }
}

// ------------- fused: aggregate (gather) + GEMM + BN stats ------------------
__global__ void __launch_bounds__(128, 2)
k_aggemm(const float* __restrict__ W, const float* __restrict__ B,
         const float* __restrict__ We, const float* __restrict__ be,
         float* __restrict__ Z, float* __restrict__ stats) {
    extern __shared__ float sm[];
    float* Ws  = sm;                  // 128*128
    float* bs  = Ws + CH * CH;        // 128
    float* Wes = bs + CH;             // 16*128
    float* bes = Wes + EF * CH;       // 128
    float* xsd = bes + CH;            // TILE*256 (duplicated)

    for (int i = threadIdx.x; i < CH * CH; i += 128) Ws[i] = W[i];
    for (int i = threadIdx.x; i < EF * CH; i += 128) Wes[i] = We[i];
    if (threadIdx.x < CH) { bs[threadIdx.x] = B[threadIdx.x]; bes[threadIdx.x] = be[threadIdx.x]; }
    __syncthreads();

    int warp = threadIdx.x >> 5, lane = threadIdx.x & 31;
    int c0 = lane * 4, r0 = warp * TR;
    unsigned long long bias0 = *(const unsigned long long*)&bs[c0];
    unsigned long long bias1 = *(const unsigned long long*)&bs[c0 + 2];

    float cs[4] = {0.f, 0.f, 0.f, 0.f};
    float cq[4] = {0.f, 0.f, 0.f, 0.f};

    for (int tile = blockIdx.x * TILE; tile < NN; tile += gridDim.x * TILE) {
        // ---- gather/aggregate phase ----
#pragma unroll 1
        for (int r = 0; r < TR; r++) {
            int n = tile + r0 + r;
            float4 acc = make_float4(0.f, 0.f, 0.f, 0.f);
            if (n < NN) {
                acc = *(const float4*)(g_h + (size_t)n * CH + c0);
                int beg = g_rowptr[n], end = g_rowptr[n + 1];
                float dg = (float)(end - beg);
                float4 b4 = *(const float4*)&bes[c0];
                acc.x += dg * b4.x; acc.y += dg * b4.y;
                acc.z += dg * b4.z; acc.w += dg * b4.w;
#pragma unroll
                for (int k = 0; k < EF; k++) {
                    float ev = g_ea[(size_t)n * EF + k];
                    float4 w = *(const float4*)&Wes[k * CH + c0];
                    acc.x += ev * w.x; acc.y += ev * w.y;
                    acc.z += ev * w.z; acc.w += ev * w.w;
                }
                int e = beg;
                for (; e + 4 <= end; e += 4) {
                    int s0 = g_col[e], s1 = g_col[e + 1];
                    int s2 = g_col[e + 2], s3 = g_col[e + 3];
                    float4 v0 = *(const float4*)(g_h + (size_t)s0 * CH + c0);
                    float4 v1 = *(const float4*)(g_h + (size_t)s1 * CH + c0);
                    float4 v2 = *(const float4*)(g_h + (size_t)s2 * CH + c0);
                    float4 v3 = *(const float4*)(g_h + (size_t)s3 * CH + c0);
                    acc.x += (v0.x + v1.x) + (v2.x + v3.x);
                    acc.y += (v0.y + v1.y) + (v2.y + v3.y);
                    acc.z += (v0.z + v1.z) + (v2.z + v3.z);
                    acc.w += (v0.w + v1.w) + (v2.w + v3.w);
                }
                for (; e < end; e++) {
                    int s = g_col[e];
                    float4 v = *(const float4*)(g_h + (size_t)s * CH + c0);
                    acc.x += v.x; acc.y += v.y; acc.z += v.z; acc.w += v.w;
                }
            }
            dup_store(xsd, r0 + r, lane, acc);
        }
        __syncthreads();

        // ---- GEMM phase ----
        gemm_tile_dup<true>(Ws, xsd, bias0, bias1, tile, r0, c0, Z, cs, cq);
        __syncthreads();
    }

    stats_flush(xsd, c0, threadIdx.x, cs, cq, stats);
}

// --- BN(from stats) + relu + residual + segmented pool, block per graph ----
__global__ void k_poolbn(const float* __restrict__ stats,
                         const float* __restrict__ gamma,
                         const float* __restrict__ beta,
                         const int* __restrict__ batch,
                         float* __restrict__ pooled) {
    __shared__ int s_lo, s_hi;
    int g = blockIdx.x, c = threadIdx.x;

    float mu = stats[c] * (1.0f / NN);
    float var = stats[CH + c] * (1.0f / NN) - mu * mu;
    float sc = gamma[c] * rsqrtf(var + BN_EPS);
    float sh = beta[c] - mu * sc;

    if (c < 2) {
        int tgt = g + c;
        int lo = 0, hi = NN;
        while (lo < hi) {
            int mid = (lo + hi) >> 1;
            if (batch[mid] < tgt) lo = mid + 1; else hi = mid;
        }
        if (c == 0) s_lo = lo; else s_hi = lo;
    }
    __syncthreads();
    int gs = s_lo, ge = s_hi;

    float a0 = 0.f, a1 = 0.f;
    int n = gs;
    for (; n + 2 <= ge; n += 2) {
        float z0 = g_z[(size_t)n * CH + c];
        float h0 = g_h[(size_t)n * CH + c];
        float z1 = g_z[(size_t)(n + 1) * CH + c];
        float h1 = g_h[(size_t)(n + 1) * CH + c];
        float o0 = fmaxf(fmaf(z0, sc, sh), 0.f) + h0;
        float o1 = fmaxf(fmaf(z1, sc, sh), 0.f) + h1;
        g_h[(size_t)n * CH + c] = o0;
        g_h[(size_t)(n + 1) * CH + c] = o1;
        a0 += o0; a1 += o1;
    }
    if (n < ge) {
        float z0 = g_z[(size_t)n * CH + c];
        float h0 = g_h[(size_t)n * CH + c];
        float o0 = fmaxf(fmaf(z0, sc, sh), 0.f) + h0;
        g_h[(size_t)n * CH + c] = o0;
        a0 += o0;
    }
    pooled[(size_t)g * CH + c] = a0 + a1;
}

// ------------------------- pool layer 0 (block per graph) ------------------
__global__ void k_pool0(const int* __restrict__ batch, float* __restrict__ pooled) {
    __shared__ int s_lo, s_hi;
    int g = blockIdx.x, c = threadIdx.x;
    if (c < 2) {
        int tgt = g + c;
        int lo = 0, hi = NN;
        while (lo < hi) {
            int mid = (lo + hi) >> 1;
            if (batch[mid] < tgt) lo = mid + 1; else hi = mid;
        }
        if (c == 0) s_lo = lo; else s_hi = lo;
    }
    __syncthreads();
    int gs = s_lo, ge = s_hi;

    float a0 = 0.f, a1 = 0.f, a2 = 0.f, a3 = 0.f;
    int n = gs;
    for (; n + 4 <= ge; n += 4) {
        a0 += g_h[(size_t)n * CH + c];
        a1 += g_h[(size_t)(n + 1) * CH + c];
        a2 += g_h[(size_t)(n + 2) * CH + c];
        a3 += g_h[(size_t)(n + 3) * CH + c];
    }
    for (; n < ge; n++) a0 += g_h[(size_t)n * CH + c];
    pooled[(size_t)g * CH + c] = (a0 + a1) + (a2 + a3);
}

// ------------------------- JK heads ----------------------------------------
__global__ void k_jk(const float* __restrict__ jkW, const float* __restrict__ jkb,
                     float* __restrict__ out) {
    int idx = blockIdx.x * blockDim.x + threadIdx.x;
    if (idx >= GG * NC) return;
    int g = idx / NC, c = idx % NC;
    float acc = 0.f;
#pragma unroll
    for (int l = 0; l < NL + 1; l++) {
        acc += jkb[l * NC + c];
        const float* p = g_pooled + ((size_t)l * GG + g) * CH;
        const float* w = jkW + l * CH * NC + c;
        float a = 0.f;
#pragma unroll 8
        for (int k = 0; k < CH; k++) a += p[k] * w[k * NC];
        acc += a;
    }
    out[idx] = acc;
}

// ------------------------- host launch -------------------------------------
extern "C" void kernel_launch(void* const* d_in, const int* in_sizes, int n_in,
                              void* d_out, int out_size) {
    (void)in_sizes; (void)n_in; (void)out_size;
    const float* h_in   = (const float*)d_in[0];
    const float* eattr  = (const float*)d_in[1];
    const int*   ei     = (const int*)d_in[2];
    const int*   batch  = (const int*)d_in[5];
    const float* embW   = (const float*)d_in[6];
    const float* embB   = (const float*)d_in[7];
    const float* convW  = (const float*)d_in[8];
    const float* convB  = (const float*)d_in[9];
    const float* convWe = (const float*)d_in[10];
    const float* convBe = (const float*)d_in[11];
    const float* gamma  = (const float*)d_in[12];
    const float* beta   = (const float*)d_in[13];
    const float* jkW    = (const float*)d_in[14];
    const float* jkb    = (const float*)d_in[15];
    float* out = (float*)d_out;

    void *p_deg, *p_pooled, *p_stats, *p_h, *p_z;
    cudaGetSymbolAddress(&p_deg, g_deg);
    cudaGetSymbolAddress(&p_pooled, g_pooled);
    cudaGetSymbolAddress(&p_stats, g_stats);
    cudaGetSymbolAddress(&p_h, g_h);
    cudaGetSymbolAddress(&p_z, g_z);

    const int smem_g = (CH * CH + CH + TILE * XSW) * (int)sizeof(float);
    const int smem_a = (CH * CH + CH + EF * CH + CH + TILE * XSW) * (int)sizeof(float);
    cudaFuncSetAttribute(k_gemm, cudaFuncAttributeMaxDynamicSharedMemorySize, smem_g);
    cudaFuncSetAttribute(k_aggemm, cudaFuncAttributeMaxDynamicSharedMemorySize, smem_a);

    cudaMemsetAsync(p_deg, 0, NN * sizeof(int));
    cudaMemsetAsync(p_stats, 0, NL * 2 * CH * sizeof(float));

    const int nb = (NN + 1023) / 1024;  // 49
    k_deg<<<(EE + 255) / 256, 256>>>(ei);          // kernel 1
    k_scan1<<<nb, 1024>>>();                       // kernel 2
    k_scan3<<<nb, 1024>>>(nb);                     // kernel 3
    k_gemm<<<296, 128, smem_g>>>(h_in, embW, embB, (float*)p_h);  // kernel 4 (profiled)
    k_fill<<<(EE + 255) / 256, 256>>>(ei);
    k_ea<<<(NN * 16 + 255) / 256, 256>>>(eattr);
    k_pool0<<<GG, CH>>>(batch, (float*)p_pooled);

    for (int l = 0; l < NL; l++) {
        k_aggemm<<<296, 128, smem_a>>>(convW + (size_t)l * CH * CH,
                                       convB + (size_t)l * CH,
                                       convWe + (size_t)l * EF * CH,
                                       convBe + (size_t)l * CH,
                                       (float*)p_z,
                                       (float*)p_stats + (size_t)l * 2 * CH);
        k_poolbn<<<GG, CH>>>((const float*)p_stats + (size_t)l * 2 * CH,
                             gamma + (size_t)l * CH, beta + (size_t)l * CH,
                             batch, (float*)p_pooled + (size_t)(l + 1) * GG * CH);
    }

    k_jk<<<(GG * NC + 255) / 256, 256>>>(jkW, jkb, out);
}

// round 8
// speedup vs baseline: 1.2974x; 1.2974x over previous
#include <cuda_runtime.h>

#define NN 50000
#define EE 800000
#define GG 500
#define CH 128
#define EF 16
#define NL 4
#define NC 10
#define BN_EPS 1e-5f

// packed-f32x2 FMA (Blackwell): d.{lo,hi} += a.{lo,hi} * b.{lo,hi}
#define FMA2(d, a, b) asm("fma.rn.f32x2 %0, %1, %2, %0;" : "+l"(d) : "l"(a), "l"(b))
#define PACK_DUP(d, x) asm("mov.b64 %0, {%1, %1};" : "=l"(d) : "r"(__float_as_uint(x)))

#define TR 8                // rows per warp
#define NWARP 8             // warps per block
#define TILE (NWARP * TR)   // 64 rows per block

// ------------------------- scratch (device globals, no allocation) ---------
__device__ __align__(16) float g_h[NN * CH];
__device__ __align__(16) float g_z[NN * CH];
__device__ __align__(16) float g_ea[NN * EF];
__device__ int   g_deg[NN];
__device__ int   g_rowptr[NN + 1];
__device__ int   g_cursor[NN];
__device__ int   g_col[EE];   // CSR: src sorted by dst
__device__ int   g_eid[EE];   // CSR: edge id sorted by dst
__device__ int   g_bsum[64];
__device__ __align__(16) float g_stats[NL * 2 * CH];
__device__ __align__(16) float g_pooled[(NL + 1) * GG * CH];

// ------------------------- degree count ------------------------------------
__global__ void k_deg(const int* __restrict__ ei) {
    int e = blockIdx.x * blockDim.x + threadIdx.x;
    if (e >= EE) return;
    atomicAdd(&g_deg[ei[EE + e]], 1);
}

// ------------------------- scan pass 1: per-block sums ---------------------
__global__ void k_scan1() {
    __shared__ int s[1024];
    int i = blockIdx.x * 1024 + threadIdx.x;
    s[threadIdx.x] = (i < NN) ? g_deg[i] : 0;
    __syncthreads();
    for (int off = 512; off > 0; off >>= 1) {
        if (threadIdx.x < off) s[threadIdx.x] += s[threadIdx.x + off];
        __syncthreads();
    }
    if (threadIdx.x == 0) g_bsum[blockIdx.x] = s[0];
}

// ------------- scan pass 2: per-block base + local scan --------------------
__global__ void k_scan3(int nb) {
    __shared__ int s[1024];
    __shared__ int base;
    if (threadIdx.x == 0) {
        int run = 0;
        for (int b = 0; b < blockIdx.x; b++) run += g_bsum[b];
        base = run;
        if (blockIdx.x == 0) g_rowptr[NN] = EE;
    }
    int i = blockIdx.x * 1024 + threadIdx.x;
    int v = (i < NN) ? g_deg[i] : 0;
    s[threadIdx.x] = v;
    __syncthreads();
    for (int off = 1; off < 1024; off <<= 1) {
        int t = (threadIdx.x >= off) ? s[threadIdx.x - off] : 0;
        __syncthreads();
        s[threadIdx.x] += t;
        __syncthreads();
    }
    if (i < NN) {
        int r = s[threadIdx.x] - v + base;
        g_rowptr[i] = r;
        g_cursor[i] = r;
    }
}

// ------------------------- CSR fill ----------------------------------------
__global__ void k_fill(const int* __restrict__ ei) {
    int e = blockIdx.x * blockDim.x + threadIdx.x;
    if (e >= EE) return;
    int d = ei[EE + e];
    int pos = atomicAdd(&g_cursor[d], 1);
    g_col[pos] = ei[e];
    g_eid[pos] = e;
}

// ------------------------- ea = segment_sum(edge_attr, dst) ----------------
__global__ void k_ea(const float* __restrict__ eattr) {
    int idx = blockIdx.x * blockDim.x + threadIdx.x;
    int n = idx >> 4;
    if (n >= NN) return;
    int k = idx & 15;
    int beg = g_rowptr[n], end = g_rowptr[n + 1];
    float a0 = 0.f, a1 = 0.f;
    int e = beg;
    for (; e + 2 <= end; e += 2) {
        int i0 = g_eid[e], i1 = g_eid[e + 1];
        a0 += eattr[(size_t)i0 * EF + k];
        a1 += eattr[(size_t)i1 * EF + k];
    }
    if (e < end) a0 += eattr[(size_t)g_eid[e] * EF + k];
    g_ea[(size_t)n * EF + k] = a0 + a1;
}

// ===================== GEMM core: 8 rows/warp, 4 cols/lane ==================
// Warp-private xs slice: no cross-warp dependency -> caller uses __syncwarp.
template <bool STATS>
__device__ __forceinline__ void gemm_tile8(
    const float* __restrict__ Ws, const float* __restrict__ xs,
    unsigned long long bias0, unsigned long long bias1,
    int tile, int r0, int c0, float* __restrict__ Z,
    float* cs, float* cq) {

    unsigned long long acc[TR][2];
#pragma unroll
    for (int r = 0; r < TR; r++) { acc[r][0] = bias0; acc[r][1] = bias1; }

#pragma unroll 2
    for (int k = 0; k < CH; k += 4) {
        float4 xv[TR];
#pragma unroll
        for (int r = 0; r < TR; r++) xv[r] = *(const float4*)&xs[(r0 + r) * CH + k];
#pragma unroll
        for (int kk = 0; kk < 4; kk++) {
            ulonglong2 w2 = *(const ulonglong2*)&Ws[(k + kk) * CH + c0];
#pragma unroll
            for (int r = 0; r < TR; r++) {
                float xr = (kk == 0) ? xv[r].x : (kk == 1) ? xv[r].y
                         : (kk == 2) ? xv[r].z : xv[r].w;
                unsigned long long xp;
                PACK_DUP(xp, xr);
                FMA2(acc[r][0], xp, w2.x);
                FMA2(acc[r][1], xp, w2.y);
            }
        }
    }

#pragma unroll
    for (int r = 0; r < TR; r++) {
        int m = tile + r0 + r;
        if (m < NN) {
            ulonglong2 o;
            o.x = acc[r][0]; o.y = acc[r][1];
            *(ulonglong2*)(Z + (size_t)m * CH + c0) = o;
            if (STATS) {
                float a0 = __uint_as_float((unsigned)acc[r][0]);
                float a1 = __uint_as_float((unsigned)(acc[r][0] >> 32));
                float a2 = __uint_as_float((unsigned)acc[r][1]);
                float a3 = __uint_as_float((unsigned)(acc[r][1] >> 32));
                cs[0] += a0; cq[0] += a0 * a0;
                cs[1] += a1; cq[1] += a1 * a1;
                cs[2] += a2; cq[2] += a2 * a2;
                cs[3] += a3; cq[3] += a3 * a3;
            }
        }
    }
}

__device__ __forceinline__ void stats_flush(float* sr, int c0, int tid,
                                            const float* cs, const float* cq,
                                            float* __restrict__ stats) {
    sr[tid] = 0.f;
    __syncthreads();
#pragma unroll
    for (int j = 0; j < 4; j++) {
        atomicAdd(&sr[c0 + j], cs[j]);
        atomicAdd(&sr[CH + c0 + j], cq[j]);
    }
    __syncthreads();
    atomicAdd(&stats[tid], sr[tid]);
}

// ------------------------- plain GEMM (embedding) ---------------------------
__global__ void __launch_bounds__(256, 2)
k_gemm(const float* __restrict__ X, const float* __restrict__ W,
       const float* __restrict__ B, float* __restrict__ Z) {
    extern __shared__ float sm[];
    float* Ws = sm;                  // 128*128
    float* bs = Ws + CH * CH;        // 128
    float* xs = bs + CH;             // TILE*128

    for (int i = threadIdx.x; i < CH * CH; i += 256) Ws[i] = W[i];
    if (threadIdx.x < CH) bs[threadIdx.x] = B[threadIdx.x];
    __syncthreads();

    int warp = threadIdx.x >> 5, lane = threadIdx.x & 31;
    int c0 = lane * 4, r0 = warp * TR;
    unsigned long long bias0 = *(const unsigned long long*)&bs[c0];
    unsigned long long bias1 = *(const unsigned long long*)&bs[c0 + 2];
    float cs[4], cq[4];

    for (int tile = blockIdx.x * TILE; tile < NN; tile += gridDim.x * TILE) {
#pragma unroll
        for (int r = 0; r < TR; r++) {
            int m = tile + r0 + r;
            float4 v = make_float4(0.f, 0.f, 0.f, 0.f);
            if (m < NN) v = *(const float4*)(X + (size_t)m * CH + c0);
            *(float4*)&xs[(r0 + r) * CH + c0] = v;
        }
        __syncwarp();   // warp-private slice: intra-warp ordering only
        gemm_tile8<false>(Ws, xs, bias0, bias1, tile, r0, c0, Z, cs, cq);
        __syncwarp();   // WAR: all lanes done reading before next overwrite
    }
}

// ------------- fused: aggregate (gather) + GEMM + BN stats ------------------
__global__ void __launch_bounds__(256, 2)
k_aggemm(const float* __restrict__ W, const float* __restrict__ B,
         const float* __restrict__ We, const float* __restrict__ be,
         float* __restrict__ Z, float* __restrict__ stats) {
    extern __shared__ float sm[];
    float* Ws  = sm;                  // 128*128
    float* bs  = Ws + CH * CH;        // 128
    float* Wes = bs + CH;             // 16*128
    float* bes = Wes + EF * CH;       // 128
    float* xs  = bes + CH;            // TILE*128

    for (int i = threadIdx.x; i < CH * CH; i += 256) Ws[i] = W[i];
    for (int i = threadIdx.x; i < EF * CH; i += 256) Wes[i] = We[i];
    if (threadIdx.x < CH) { bs[threadIdx.x] = B[threadIdx.x]; bes[threadIdx.x] = be[threadIdx.x]; }
    __syncthreads();

    int warp = threadIdx.x >> 5, lane = threadIdx.x & 31;
    int c0 = lane * 4, r0 = warp * TR;
    unsigned long long bias0 = *(const unsigned long long*)&bs[c0];
    unsigned long long bias1 = *(const unsigned long long*)&bs[c0 + 2];

    float cs[4] = {0.f, 0.f, 0.f, 0.f};
    float cq[4] = {0.f, 0.f, 0.f, 0.f};

    for (int tile = blockIdx.x * TILE; tile < NN; tile += gridDim.x * TILE) {
        // ---- gather/aggregate phase (warp-private rows) ----
#pragma unroll 1
        for (int r = 0; r < TR; r++) {
            int n = tile + r0 + r;
            float4 acc = make_float4(0.f, 0.f, 0.f, 0.f);
            if (n < NN) {
                acc = *(const float4*)(g_h + (size_t)n * CH + c0);
                int beg = g_rowptr[n], end = g_rowptr[n + 1];
                float dg = (float)(end - beg);
                float4 b4 = *(const float4*)&bes[c0];
                acc.x += dg * b4.x; acc.y += dg * b4.y;
                acc.z += dg * b4.z; acc.w += dg * b4.w;
#pragma unroll
                for (int k = 0; k < EF; k++) {
                    float ev = g_ea[(size_t)n * EF + k];
                    float4 w = *(const float4*)&Wes[k * CH + c0];
                    acc.x += ev * w.x; acc.y += ev * w.y;
                    acc.z += ev * w.z; acc.w += ev * w.w;
                }
                int e = beg;
                for (; e + 4 <= end; e += 4) {
                    int s0 = g_col[e], s1 = g_col[e + 1];
                    int s2 = g_col[e + 2], s3 = g_col[e + 3];
                    float4 v0 = *(const float4*)(g_h + (size_t)s0 * CH + c0);
                    float4 v1 = *(const float4*)(g_h + (size_t)s1 * CH + c0);
                    float4 v2 = *(const float4*)(g_h + (size_t)s2 * CH + c0);
                    float4 v3 = *(const float4*)(g_h + (size_t)s3 * CH + c0);
                    acc.x += (v0.x + v1.x) + (v2.x + v3.x);
                    acc.y += (v0.y + v1.y) + (v2.y + v3.y);
                    acc.z += (v0.z + v1.z) + (v2.z + v3.z);
                    acc.w += (v0.w + v1.w) + (v2.w + v3.w);
                }
                for (; e < end; e++) {
                    int s = g_col[e];
                    float4 v = *(const float4*)(g_h + (size_t)s * CH + c0);
                    acc.x += v.x; acc.y += v.y; acc.z += v.z; acc.w += v.w;
                }
            }
            *(float4*)&xs[(r0 + r) * CH + c0] = acc;
        }
        __syncwarp();   // warp-private slice: intra-warp ordering only
        gemm_tile8<true>(Ws, xs, bias0, bias1, tile, r0, c0, Z, cs, cq);
        __syncwarp();   // WAR before next gather overwrites the slice
    }

    __syncthreads();    // all warps done before reusing xs as scratch
    stats_flush(xs, c0, threadIdx.x, cs, cq, stats);
}

// --- BN(from stats) + relu + residual + segmented pool, block per graph ----
__global__ void k_poolbn(const float* __restrict__ stats,
                         const float* __restrict__ gamma,
                         const float* __restrict__ beta,
                         const int* __restrict__ batch,
                         float* __restrict__ pooled) {
    __shared__ int s_lo, s_hi;
    int g = blockIdx.x, c = threadIdx.x;

    float mu = stats[c] * (1.0f / NN);
    float var = stats[CH + c] * (1.0f / NN) - mu * mu;
    float sc = gamma[c] * rsqrtf(var + BN_EPS);
    float sh = beta[c] - mu * sc;

    if (c < 2) {
        int tgt = g + c;
        int lo = 0, hi = NN;
        while (lo < hi) {
            int mid = (lo + hi) >> 1;
            if (batch[mid] < tgt) lo = mid + 1; else hi = mid;
        }
        if (c == 0) s_lo = lo; else s_hi = lo;
    }
    __syncthreads();
    int gs = s_lo, ge = s_hi;

    float a0 = 0.f, a1 = 0.f;
    int n = gs;
    for (; n + 2 <= ge; n += 2) {
        float z0 = g_z[(size_t)n * CH + c];
        float h0 = g_h[(size_t)n * CH + c];
        float z1 = g_z[(size_t)(n + 1) * CH + c];
        float h1 = g_h[(size_t)(n + 1) * CH + c];
        float o0 = fmaxf(fmaf(z0, sc, sh), 0.f) + h0;
        float o1 = fmaxf(fmaf(z1, sc, sh), 0.f) + h1;
        g_h[(size_t)n * CH + c] = o0;
        g_h[(size_t)(n + 1) * CH + c] = o1;
        a0 += o0; a1 += o1;
    }
    if (n < ge) {
        float z0 = g_z[(size_t)n * CH + c];
        float h0 = g_h[(size_t)n * CH + c];
        float o0 = fmaxf(fmaf(z0, sc, sh), 0.f) + h0;
        g_h[(size_t)n * CH + c] = o0;
        a0 += o0;
    }
    pooled[(size_t)g * CH + c] = a0 + a1;
}

// ------------------------- pool layer 0 (block per graph) ------------------
__global__ void k_pool0(const int* __restrict__ batch, float* __restrict__ pooled) {
    __shared__ int s_lo, s_hi;
    int g = blockIdx.x, c = threadIdx.x;
    if (c < 2) {
        int tgt = g + c;
        int lo = 0, hi = NN;
        while (lo < hi) {
            int mid = (lo + hi) >> 1;
            if (batch[mid] < tgt) lo = mid + 1; else hi = mid;
        }
        if (c == 0) s_lo = lo; else s_hi = lo;
    }
    __syncthreads();
    int gs = s_lo, ge = s_hi;

    float a0 = 0.f, a1 = 0.f, a2 = 0.f, a3 = 0.f;
    int n = gs;
    for (; n + 4 <= ge; n += 4) {
        a0 += g_h[(size_t)n * CH + c];
        a1 += g_h[(size_t)(n + 1) * CH + c];
        a2 += g_h[(size_t)(n + 2) * CH + c];
        a3 += g_h[(size_t)(n + 3) * CH + c];
    }
    for (; n < ge; n++) a0 += g_h[(size_t)n * CH + c];
    pooled[(size_t)g * CH + c] = (a0 + a1) + (a2 + a3);
}

// ------------------------- JK heads ----------------------------------------
__global__ void k_jk(const float* __restrict__ jkW, const float* __restrict__ jkb,
                     float* __restrict__ out) {
    int idx = blockIdx.x * blockDim.x + threadIdx.x;
    if (idx >= GG * NC) return;
    int g = idx / NC, c = idx % NC;
    float acc = 0.f;
#pragma unroll
    for (int l = 0; l < NL + 1; l++) {
        acc += jkb[l * NC + c];
        const float* p = g_pooled + ((size_t)l * GG + g) * CH;
        const float* w = jkW + l * CH * NC + c;
        float a = 0.f;
#pragma unroll 8
        for (int k = 0; k < CH; k++) a += p[k] * w[k * NC];
        acc += a;
    }
    out[idx] = acc;
}

// ------------------------- host launch -------------------------------------
extern "C" void kernel_launch(void* const* d_in, const int* in_sizes, int n_in,
                              void* d_out, int out_size) {
    (void)in_sizes; (void)n_in; (void)out_size;
    const float* h_in   = (const float*)d_in[0];
    const float* eattr  = (const float*)d_in[1];
    const int*   ei     = (const int*)d_in[2];
    const int*   batch  = (const int*)d_in[5];
    const float* embW   = (const float*)d_in[6];
    const float* embB   = (const float*)d_in[7];
    const float* convW  = (const float*)d_in[8];
    const float* convB  = (const float*)d_in[9];
    const float* convWe = (const float*)d_in[10];
    const float* convBe = (const float*)d_in[11];
    const float* gamma  = (const float*)d_in[12];
    const float* beta   = (const float*)d_in[13];
    const float* jkW    = (const float*)d_in[14];
    const float* jkb    = (const float*)d_in[15];
    float* out = (float*)d_out;

    void *p_deg, *p_pooled, *p_stats, *p_h, *p_z;
    cudaGetSymbolAddress(&p_deg, g_deg);
    cudaGetSymbolAddress(&p_pooled, g_pooled);
    cudaGetSymbolAddress(&p_stats, g_stats);
    cudaGetSymbolAddress(&p_h, g_h);
    cudaGetSymbolAddress(&p_z, g_z);

    const int smem_g = (CH * CH + CH + TILE * CH) * (int)sizeof(float);
    const int smem_a = (CH * CH + CH + EF * CH + CH + TILE * CH) * (int)sizeof(float);
    cudaFuncSetAttribute(k_gemm, cudaFuncAttributeMaxDynamicSharedMemorySize, smem_g);
    cudaFuncSetAttribute(k_aggemm, cudaFuncAttributeMaxDynamicSharedMemorySize, smem_a);

    cudaMemsetAsync(p_deg, 0, NN * sizeof(int));
    cudaMemsetAsync(p_stats, 0, NL * 2 * CH * sizeof(float));

    const int nb = (NN + 1023) / 1024;  // 49
    k_deg<<<(EE + 255) / 256, 256>>>(ei);          // kernel 1
    k_scan1<<<nb, 1024>>>();                       // kernel 2
    k_scan3<<<nb, 1024>>>(nb);                     // kernel 3
    k_gemm<<<296, 256, smem_g>>>(h_in, embW, embB, (float*)p_h);  // kernel 4 (profiled)
    k_fill<<<(EE + 255) / 256, 256>>>(ei);
    k_ea<<<(NN * 16 + 255) / 256, 256>>>(eattr);
    k_pool0<<<GG, CH>>>(batch, (float*)p_pooled);

    for (int l = 0; l < NL; l++) {
        k_aggemm<<<296, 256, smem_a>>>(convW + (size_t)l * CH * CH,
                                       convB + (size_t)l * CH,
                                       convWe + (size_t)l * EF * CH,
                                       convBe + (size_t)l * CH,
                                       (float*)p_z,
                                       (float*)p_stats + (size_t)l * 2 * CH);
        k_poolbn<<<GG, CH>>>((const float*)p_stats + (size_t)l * 2 * CH,
                             gamma + (size_t)l * CH, beta + (size_t)l * CH,
                             batch, (float*)p_pooled + (size_t)(l + 1) * GG * CH);
    }

    k_jk<<<(GG * NC + 255) / 256, 256>>>(jkW, jkb, out);
}